// round 1
// baseline (speedup 1.0000x reference)
#include <cuda_runtime.h>
#include <cstdint>

#define NN  30000
#define NE  960000
#define HID 300
#define LD  320      // padded row stride for internal [N,H] buffers (tail zeroed)
#define VOC 10000

// ---------------- scratch (device globals: no allocs allowed) ----------------
__device__ float g_h0[NN * LD];
__device__ float g_h1[NN * LD];
__device__ float g_agg[NN * LD];
__device__ int   g_deg[NN];
__device__ float g_inv[NN];
__device__ int   g_row[NN + 1];
__device__ int   g_nxt[NN];
__device__ int   g_col[NE];

// ---------------- CSR build ----------------
__global__ void k_zero() {
    int i = blockIdx.x * blockDim.x + threadIdx.x;
    if (i < NN) g_deg[i] = 0;
}

__global__ void k_hist(const int* __restrict__ ei) {
    int e = blockIdx.x * blockDim.x + threadIdx.x;
    if (e < NE) atomicAdd(&g_deg[ei[NE + e]], 1);
}

__global__ void k_scan() {
    __shared__ int part[1024];
    int t = threadIdx.x;
    int s = t * 30;
    int e = min(s + 30, NN);
    int sum = 0;
    for (int i = s; i < e; i++) sum += g_deg[i];
    part[t] = sum;
    __syncthreads();
    for (int off = 1; off < 1024; off <<= 1) {
        int v = (t >= off) ? part[t - off] : 0;
        __syncthreads();
        part[t] += v;
        __syncthreads();
    }
    int run = (t == 0) ? 0 : part[t - 1];
    for (int i = s; i < e; i++) {
        int d = g_deg[i];
        g_row[i] = run;
        g_nxt[i] = run;
        g_inv[i] = (d > 0) ? 1.0f / (float)d : 0.0f;
        run += d;
    }
    if (t == 1023) g_row[NN] = run;
}

__global__ void k_fill(const int* __restrict__ ei) {
    int e = blockIdx.x * blockDim.x + threadIdx.x;
    if (e < NE) {
        int src = ei[e];
        int dst = ei[NE + e];
        int p = atomicAdd(&g_nxt[dst], 1);
        g_col[p] = src;
    }
}

// ---------------- embedding gather (warp per node) ----------------
__global__ void k_embed(const int* __restrict__ x, const float* __restrict__ emb) {
    int node = (blockIdx.x * blockDim.x + threadIdx.x) >> 5;
    int lane = threadIdx.x & 31;
    if (node >= NN) return;
    const float4* src = (const float4*)(emb + (size_t)x[node] * HID);
    float4* dst = (float4*)(g_h0 + (size_t)node * LD);
    for (int i = lane; i < LD / 4; i += 32) {     // 80 float4 per row
        float4 v = make_float4(0.f, 0.f, 0.f, 0.f);
        if (i < HID / 4) v = src[i];              // 75 valid
        dst[i] = v;
    }
}

// ---------------- scatter-mean aggregation (warp per dst node, CSR) ----------------
__global__ void k_agg(const float* __restrict__ hin) {
    int node = (blockIdx.x * blockDim.x + threadIdx.x) >> 5;
    int lane = threadIdx.x & 31;
    if (node >= NN) return;
    float acc[10];
#pragma unroll
    for (int i = 0; i < 10; i++) acc[i] = 0.f;
    int s = g_row[node], e = g_row[node + 1];
    for (int j = s; j < e; j++) {
        const float* r = hin + (size_t)g_col[j] * LD;
#pragma unroll
        for (int i = 0; i < 10; i++) {
            int c = lane + 32 * i;
            if (c < HID) acc[i] += r[c];
        }
    }
    float w = g_inv[node];
    float* out = g_agg + (size_t)node * LD;
#pragma unroll
    for (int i = 0; i < 10; i++) {
        int c = lane + 32 * i;
        out[c] = (c < HID) ? acc[i] * w : 0.f;
    }
}

// ---------------- fused layer GEMM: C = relu(A0@B0 + A1@B1 + bias), fp32 ----------------
// A: [NN, LD] (padded, tail zero). B: [300,300]. C: [NN, LD] with zero tail.
__global__ void __launch_bounds__(256) k_layer(
    const float* __restrict__ A0, const float* __restrict__ A1,
    const float* __restrict__ B0, const float* __restrict__ B1,
    const float* __restrict__ bias, float* __restrict__ C)
{
    __shared__ float As[2][64][16];
    __shared__ float Bs[2][16][64];
    int tid = threadIdx.x;
    int tx = tid & 15, ty = tid >> 4;
    int m0 = blockIdx.x * 64, n0 = blockIdx.y * 64;
    float acc[4][4];
#pragma unroll
    for (int i = 0; i < 4; i++)
#pragma unroll
        for (int j = 0; j < 4; j++) acc[i][j] = 0.f;

    int ar = tid >> 2;            // 0..63
    int ac = (tid & 3) * 4;       // 0,4,8,12
    int br = tid >> 4;            // 0..15
    int bc = (tid & 15) * 4;      // 0..60

    for (int k0 = 0; k0 < HID; k0 += 16) {      // 19 iters, covers k 0..303 (A pad zeros)
        float4 z = make_float4(0.f, 0.f, 0.f, 0.f);
        int gm = m0 + ar;
        float4 va = z, vb = z;
        if (gm < NN) {
            va = *(const float4*)(A0 + (size_t)gm * LD + k0 + ac);
            vb = *(const float4*)(A1 + (size_t)gm * LD + k0 + ac);
        }
        *(float4*)&As[0][ar][ac] = va;
        *(float4*)&As[1][ar][ac] = vb;

        int gk = k0 + br;
        int gn = n0 + bc;
        float4 w0 = z, w1 = z;
        if (gk < HID && gn < HID) {   // gn%4==0, HID%4==0 -> full float4 valid
            w0 = *(const float4*)(B0 + (size_t)gk * HID + gn);
            w1 = *(const float4*)(B1 + (size_t)gk * HID + gn);
        }
        *(float4*)&Bs[0][br][bc] = w0;
        *(float4*)&Bs[1][br][bc] = w1;
        __syncthreads();

#pragma unroll
        for (int kk = 0; kk < 16; kk++) {
            float a0[4], a1[4];
#pragma unroll
            for (int i = 0; i < 4; i++) {
                a0[i] = As[0][ty * 4 + i][kk];
                a1[i] = As[1][ty * 4 + i][kk];
            }
            float4 b0 = *(const float4*)&Bs[0][kk][tx * 4];
            float4 b1 = *(const float4*)&Bs[1][kk][tx * 4];
#pragma unroll
            for (int i = 0; i < 4; i++) {
                acc[i][0] += a0[i] * b0.x + a1[i] * b1.x;
                acc[i][1] += a0[i] * b0.y + a1[i] * b1.y;
                acc[i][2] += a0[i] * b0.z + a1[i] * b1.z;
                acc[i][3] += a0[i] * b0.w + a1[i] * b1.w;
            }
        }
        __syncthreads();
    }

#pragma unroll
    for (int i = 0; i < 4; i++) {
        int row = m0 + ty * 4 + i;
        if (row >= NN) continue;
#pragma unroll
        for (int j = 0; j < 4; j++) {
            int col = n0 + tx * 4 + j;     // < 320 always (grid.y = 5)
            float v = 0.f;
            if (col < HID) v = fmaxf(acc[i][j] + bias[col], 0.f);
            C[(size_t)row * LD + col] = v;
        }
    }
}

// ---------------- final GEMM: O = H@W + bias, tf32 mma.sync ----------------
__device__ __forceinline__ uint32_t f2tf(float f) {
    uint32_t r;
    asm("cvt.rna.tf32.f32 %0, %1;" : "=r"(r) : "f"(f));
    return r;
}

__device__ __forceinline__ void mma8(float* d, const uint32_t* a, const uint32_t* b) {
    asm volatile(
        "mma.sync.aligned.m16n8k8.row.col.f32.tf32.tf32.f32 "
        "{%0,%1,%2,%3}, {%4,%5,%6,%7}, {%8,%9}, {%0,%1,%2,%3};\n"
        : "+f"(d[0]), "+f"(d[1]), "+f"(d[2]), "+f"(d[3])
        : "r"(a[0]), "r"(a[1]), "r"(a[2]), "r"(a[3]), "r"(b[0]), "r"(b[1]));
}

// BM=128, BN=64, BK=32; 4 warps in 2x2; warp tile 64x32 (4 m-tiles x 4 n-tiles of 16x8)
__global__ void __launch_bounds__(128) k_final(
    const float* __restrict__ H, const float* __restrict__ W,
    const float* __restrict__ bias, float* __restrict__ O)
{
    __shared__ uint32_t As[128][36];   // stride 36: frag bank = lane id (conflict-free)
    __shared__ uint32_t Bs[32][72];    // stride 72: frag bank = 8(T%4)+T/4 (conflict-free)
    int tid = threadIdx.x;
    int lane = tid & 31, warp = tid >> 5;
    int wm = warp >> 1, wn = warp & 1;
    int m0 = blockIdx.y * 128, n0 = blockIdx.x * 64;

    float acc[4][4][4];
#pragma unroll
    for (int mt = 0; mt < 4; mt++)
#pragma unroll
        for (int nt = 0; nt < 4; nt++)
#pragma unroll
            for (int q = 0; q < 4; q++) acc[mt][nt][q] = 0.f;

    int arow = tid >> 3;           // 0..15
    int acol = (tid & 7) * 4;      // 0..28
    int brow = tid >> 4;           // 0..7
    int bcol = (tid & 15) * 4;     // 0..60

    for (int k0 = 0; k0 < LD; k0 += 32) {   // 10 iters; k>=300 reads A pad zeros, B guarded
#pragma unroll
        for (int p = 0; p < 8; p++) {
            int r = p * 16 + arow;
            int gm = m0 + r;
            float4 v = make_float4(0.f, 0.f, 0.f, 0.f);
            if (gm < NN) v = *(const float4*)(H + (size_t)gm * LD + k0 + acol);
            As[r][acol + 0] = f2tf(v.x);
            As[r][acol + 1] = f2tf(v.y);
            As[r][acol + 2] = f2tf(v.z);
            As[r][acol + 3] = f2tf(v.w);
        }
#pragma unroll
        for (int p = 0; p < 4; p++) {
            int r = p * 8 + brow;
            int gk = k0 + r;
            int gn = n0 + bcol;
            float4 v = make_float4(0.f, 0.f, 0.f, 0.f);
            if (gk < HID && gn < VOC) v = *(const float4*)(W + (size_t)gk * VOC + gn);
            Bs[r][bcol + 0] = f2tf(v.x);
            Bs[r][bcol + 1] = f2tf(v.y);
            Bs[r][bcol + 2] = f2tf(v.z);
            Bs[r][bcol + 3] = f2tf(v.w);
        }
        __syncthreads();

#pragma unroll
        for (int k8 = 0; k8 < 4; k8++) {
            uint32_t a[4][4], b[4][2];
#pragma unroll
            for (int mt = 0; mt < 4; mt++) {
                int r = wm * 64 + mt * 16 + (lane >> 2);
                int c = k8 * 8 + (lane & 3);
                a[mt][0] = As[r][c];
                a[mt][1] = As[r + 8][c];
                a[mt][2] = As[r][c + 4];
                a[mt][3] = As[r + 8][c + 4];
            }
#pragma unroll
            for (int nt = 0; nt < 4; nt++) {
                int cc = wn * 32 + nt * 8 + (lane >> 2);
                int rr = k8 * 8 + (lane & 3);
                b[nt][0] = Bs[rr][cc];
                b[nt][1] = Bs[rr + 4][cc];
            }
#pragma unroll
            for (int mt = 0; mt < 4; mt++)
#pragma unroll
                for (int nt = 0; nt < 4; nt++)
                    mma8(acc[mt][nt], a[mt], b[nt]);
        }
        __syncthreads();
    }

#pragma unroll
    for (int mt = 0; mt < 4; mt++) {
        int r0 = m0 + wm * 64 + mt * 16 + (lane >> 2);
#pragma unroll
        for (int nt = 0; nt < 4; nt++) {
            int c = n0 + wn * 32 + nt * 8 + (lane & 3) * 2;
            if (c >= VOC) continue;
            float bv0 = bias[c], bv1 = bias[c + 1];
            if (r0 < NN) {
                float2 v = make_float2(acc[mt][nt][0] + bv0, acc[mt][nt][1] + bv1);
                *(float2*)(O + (size_t)r0 * VOC + c) = v;
            }
            if (r0 + 8 < NN) {
                float2 v = make_float2(acc[mt][nt][2] + bv0, acc[mt][nt][3] + bv1);
                *(float2*)(O + (size_t)(r0 + 8) * VOC + c) = v;
            }
        }
    }
}

// ---------------- launcher ----------------
extern "C" void kernel_launch(void* const* d_in, const int* in_sizes, int n_in,
                              void* d_out, int out_size)
{
    (void)in_sizes; (void)n_in; (void)out_size;
    const int*   x     = (const int*)d_in[0];
    const int*   ei    = (const int*)d_in[1];
    const float* emb   = (const float*)d_in[2];
    const float* Wl    = (const float*)d_in[3];
    const float* bl    = (const float*)d_in[4];
    const float* Wr    = (const float*)d_in[5];
    const float* Wlast = (const float*)d_in[6];
    const float* blast = (const float*)d_in[7];
    float* out = (float*)d_out;

    float *h0, *h1, *agg;
    cudaGetSymbolAddress((void**)&h0, g_h0);
    cudaGetSymbolAddress((void**)&h1, g_h1);
    cudaGetSymbolAddress((void**)&agg, g_agg);

    k_zero<<<(NN + 255) / 256, 256>>>();
    k_hist<<<(NE + 255) / 256, 256>>>(ei);
    k_scan<<<1, 1024>>>();
    k_fill<<<(NE + 255) / 256, 256>>>(ei);
    k_embed<<<(NN * 32 + 127) / 128, 128>>>(x, emb);

    float* cur = h0;
    float* nxt = h1;
    for (int l = 0; l < 3; l++) {
        k_agg<<<(NN * 32 + 127) / 128, 128>>>(cur);
        k_layer<<<dim3((NN + 63) / 64, LD / 64), 256>>>(
            agg, cur, Wl + (size_t)l * HID * HID, Wr + (size_t)l * HID * HID,
            bl + (size_t)l * HID, nxt);
        float* t = cur; cur = nxt; nxt = t;
    }
    k_final<<<dim3((VOC + 63) / 64, (NN + 127) / 128), 128>>>(cur, Wlast, blast, out);
}

// round 6
// speedup vs baseline: 2.0873x; 2.0873x over previous
#include <cuda_runtime.h>
#include <cstdint>

#define NN  30000
#define NE  960000
#define HID 300
#define LD  320      // padded row stride for internal [N,H] buffers (tail zeroed)
#define VOC 10000

// ---------------- scratch (device globals: no allocs allowed) ----------------
__device__ float g_h0[NN * LD];
__device__ float g_h1[NN * LD];
__device__ float g_agg[NN * LD];
__device__ int   g_deg[NN];
__device__ float g_inv[NN];
__device__ int   g_row[NN + 1];
__device__ int   g_nxt[NN];
__device__ int   g_col[NE];

// ---------------- CSR build ----------------
__global__ void k_zero() {
    int i = blockIdx.x * blockDim.x + threadIdx.x;
    if (i < NN) g_deg[i] = 0;
}

__global__ void k_hist(const int* __restrict__ ei) {
    int e = blockIdx.x * blockDim.x + threadIdx.x;
    if (e < NE) atomicAdd(&g_deg[ei[NE + e]], 1);
}

__global__ void k_scan() {
    __shared__ int part[1024];
    int t = threadIdx.x;
    int s = t * 30;
    int e = min(s + 30, NN);
    int sum = 0;
    for (int i = s; i < e; i++) sum += g_deg[i];
    part[t] = sum;
    __syncthreads();
    for (int off = 1; off < 1024; off <<= 1) {
        int v = (t >= off) ? part[t - off] : 0;
        __syncthreads();
        part[t] += v;
        __syncthreads();
    }
    int run = (t == 0) ? 0 : part[t - 1];
    for (int i = s; i < e; i++) {
        int d = g_deg[i];
        g_row[i] = run;
        g_nxt[i] = run;
        g_inv[i] = (d > 0) ? 1.0f / (float)d : 0.0f;
        run += d;
    }
    if (t == 1023) g_row[NN] = run;
}

__global__ void k_fill(const int* __restrict__ ei) {
    int e = blockIdx.x * blockDim.x + threadIdx.x;
    if (e < NE) {
        int src = ei[e];
        int dst = ei[NE + e];
        int p = atomicAdd(&g_nxt[dst], 1);
        g_col[p] = src;
    }
}

// ---------------- embedding gather (warp per node) ----------------
__global__ void k_embed(const int* __restrict__ x, const float* __restrict__ emb) {
    int node = (blockIdx.x * blockDim.x + threadIdx.x) >> 5;
    int lane = threadIdx.x & 31;
    if (node >= NN) return;
    const float4* src = (const float4*)(emb + (size_t)x[node] * HID);
    float4* dst = (float4*)(g_h0 + (size_t)node * LD);
    for (int i = lane; i < LD / 4; i += 32) {     // 80 float4 per row
        float4 v = make_float4(0.f, 0.f, 0.f, 0.f);
        if (i < HID / 4) v = src[i];              // 75 valid
        dst[i] = v;
    }
}

// ---------------- scatter-mean aggregation (warp per dst node, CSR, float4) --
__global__ void k_agg(const float* __restrict__ hin) {
    int node = (blockIdx.x * blockDim.x + threadIdx.x) >> 5;
    int lane = threadIdx.x & 31;
    if (node >= NN) return;
    float4 a0 = make_float4(0.f, 0.f, 0.f, 0.f);
    float4 a1 = a0, a2 = a0;
    int s = g_row[node], e = g_row[node + 1];
    for (int j = s; j < e; j++) {
        const float4* r = (const float4*)(hin + (size_t)g_col[j] * LD);
        float4 v0 = r[lane];
        float4 v1 = r[lane + 32];
        a0.x += v0.x; a0.y += v0.y; a0.z += v0.z; a0.w += v0.w;
        a1.x += v1.x; a1.y += v1.y; a1.z += v1.z; a1.w += v1.w;
        if (lane < 16) {
            float4 v2 = r[lane + 64];
            a2.x += v2.x; a2.y += v2.y; a2.z += v2.z; a2.w += v2.w;
        }
    }
    float w = g_inv[node];
    float4* out = (float4*)(g_agg + (size_t)node * LD);
    a0.x *= w; a0.y *= w; a0.z *= w; a0.w *= w;
    a1.x *= w; a1.y *= w; a1.z *= w; a1.w *= w;
    out[lane] = a0;
    out[lane + 32] = a1;
    if (lane < 16) {
        a2.x *= w; a2.y *= w; a2.z *= w; a2.w *= w;
        out[lane + 64] = a2;   // includes zero-pad chunks (stay zero)
    }
}

// ---------------- tf32 helpers ----------------
__device__ __forceinline__ uint32_t f2tf(float f) {
    uint32_t r;
    asm("cvt.rna.tf32.f32 %0, %1;" : "=r"(r) : "f"(f));
    return r;
}

__device__ __forceinline__ void mma8(float* d, const uint32_t* a, const uint32_t* b) {
    asm volatile(
        "mma.sync.aligned.m16n8k8.row.col.f32.tf32.tf32.f32 "
        "{%0,%1,%2,%3}, {%4,%5,%6,%7}, {%8,%9}, {%0,%1,%2,%3};\n"
        : "+f"(d[0]), "+f"(d[1]), "+f"(d[2]), "+f"(d[3])
        : "r"(a[0]), "r"(a[1]), "r"(a[2]), "r"(a[3]), "r"(b[0]), "r"(b[1]));
}

// ================= layer GEMM helpers (no lambdas) ==========================
// BM=128, BN=64, BK=16; 256 threads, 8 warps (4x2); warp tile 32x32.
// Static smem: As 2*128*20*4 + Bs 2*16*72*4 = 29696 B  (< 48 KB)

__device__ __forceinline__ void l_load(
    int t, const float* __restrict__ A0, const float* __restrict__ A1,
    const float* __restrict__ B0, const float* __restrict__ B1,
    int m0, int n0, int arow, int acol, int brow, int bcol,
    float4& ra0, float4& ra1, float4& rb)
{
    const float4 z4 = make_float4(0.f, 0.f, 0.f, 0.f);
    int s = (t >= 20) ? 1 : 0;
    int k0 = (t - s * 20) * 16;
    const float* A = s ? A1 : A0;
    const float* B = s ? B1 : B0;
    int gm0 = m0 + arow;
    int gm1 = m0 + 64 + arow;
    ra0 = (gm0 < NN) ? *(const float4*)(A + (size_t)gm0 * LD + k0 + acol) : z4;
    ra1 = (gm1 < NN) ? *(const float4*)(A + (size_t)gm1 * LD + k0 + acol) : z4;
    int gk = k0 + brow;
    rb = (gk < HID) ? *(const float4*)(B + (size_t)gk * HID + n0 + bcol) : z4;
}

__device__ __forceinline__ void l_store(
    uint32_t (*As)[20], uint32_t (*Bs)[72],
    int arow, int acol, int brow, int bcol,
    const float4& ra0, const float4& ra1, const float4& rb)
{
    uint32_t* r0 = &As[arow][acol];
    r0[0] = f2tf(ra0.x); r0[1] = f2tf(ra0.y); r0[2] = f2tf(ra0.z); r0[3] = f2tf(ra0.w);
    uint32_t* r1 = &As[64 + arow][acol];
    r1[0] = f2tf(ra1.x); r1[1] = f2tf(ra1.y); r1[2] = f2tf(ra1.z); r1[3] = f2tf(ra1.w);
    uint32_t* rB = &Bs[brow][bcol];
    rB[0] = f2tf(rb.x); rB[1] = f2tf(rb.y); rB[2] = f2tf(rb.z); rB[3] = f2tf(rb.w);
}

__device__ __forceinline__ void l_compute(
    const uint32_t (*As)[20], const uint32_t (*Bs)[72],
    float (&acc)[2][4][4], int wm, int wn, int lane)
{
#pragma unroll
    for (int k8 = 0; k8 < 2; k8++) {
        uint32_t a[2][4], b[4][2];
#pragma unroll
        for (int mt = 0; mt < 2; mt++) {
            int r = wm * 32 + mt * 16 + (lane >> 2);
            int c = k8 * 8 + (lane & 3);
            a[mt][0] = As[r][c];
            a[mt][1] = As[r + 8][c];
            a[mt][2] = As[r][c + 4];
            a[mt][3] = As[r + 8][c + 4];
        }
#pragma unroll
        for (int nt = 0; nt < 4; nt++) {
            int cc = wn * 32 + nt * 8 + (lane >> 2);
            int rr = k8 * 8 + (lane & 3);
            b[nt][0] = Bs[rr][cc];
            b[nt][1] = Bs[rr + 4][cc];
        }
#pragma unroll
        for (int mt = 0; mt < 2; mt++)
#pragma unroll
            for (int nt = 0; nt < 4; nt++)
                mma8(acc[mt][nt], a[mt], b[nt]);
    }
}

__global__ void __launch_bounds__(256) k_layer(
    const float* __restrict__ A0, const float* __restrict__ A1,
    const float* __restrict__ B0, const float* __restrict__ B1,
    const float* __restrict__ bias, float* __restrict__ C)
{
    __shared__ uint32_t As[2][128][20];
    __shared__ uint32_t Bs[2][16][72];
    const int tid = threadIdx.x, lane = tid & 31, warp = tid >> 5;
    const int wm = warp >> 1, wn = warp & 1;
    const int m0 = blockIdx.x * 128, n0 = blockIdx.y * 64;

    float acc[2][4][4];
#pragma unroll
    for (int mt = 0; mt < 2; mt++)
#pragma unroll
        for (int nt = 0; nt < 4; nt++)
#pragma unroll
            for (int q = 0; q < 4; q++) acc[mt][nt][q] = 0.f;

    const int arow = tid >> 2;          // 0..63
    const int acol = (tid & 3) * 4;     // 0,4,8,12
    const int brow = tid >> 4;          // 0..15
    const int bcol = (tid & 15) * 4;    // 0..60

    float4 ra0, ra1, rb;

    l_load(0, A0, A1, B0, B1, m0, n0, arow, acol, brow, bcol, ra0, ra1, rb);
    l_store(As[0], Bs[0], arow, acol, brow, bcol, ra0, ra1, rb);
    __syncthreads();
    for (int t = 0; t < 40; t++) {
        int cur = t & 1;
        if (t < 39)
            l_load(t + 1, A0, A1, B0, B1, m0, n0, arow, acol, brow, bcol, ra0, ra1, rb);
        l_compute(As[cur], Bs[cur], acc, wm, wn, lane);
        if (t < 39) {
            l_store(As[cur ^ 1], Bs[cur ^ 1], arow, acol, brow, bcol, ra0, ra1, rb);
            __syncthreads();
        }
    }

#pragma unroll
    for (int mt = 0; mt < 2; mt++) {
        int r0 = m0 + wm * 32 + mt * 16 + (lane >> 2);
#pragma unroll
        for (int nt = 0; nt < 4; nt++) {
            int c = n0 + wn * 32 + nt * 8 + (lane & 3) * 2;   // even, < 320
            float v0 = 0.f, v1 = 0.f, v2 = 0.f, v3 = 0.f;
            if (c < HID) {   // c even, HID even -> c+1 also < HID
                float bv0 = bias[c], bv1 = bias[c + 1];
                v0 = fmaxf(acc[mt][nt][0] + bv0, 0.f);
                v1 = fmaxf(acc[mt][nt][1] + bv1, 0.f);
                v2 = fmaxf(acc[mt][nt][2] + bv0, 0.f);
                v3 = fmaxf(acc[mt][nt][3] + bv1, 0.f);
            }
            if (r0 < NN)
                *(float2*)(C + (size_t)r0 * LD + c) = make_float2(v0, v1);
            if (r0 + 8 < NN)
                *(float2*)(C + (size_t)(r0 + 8) * LD + c) = make_float2(v2, v3);
        }
    }
}

// ================= final GEMM helpers (no lambdas) ==========================
// BM=128, BN=128, BK=16; 256 threads, 8 warps (2x4); warp tile 64x32.
// Static smem: As 2*128*20*4 + Bs 2*16*136*4 = 37888 B  (< 48 KB)

__device__ __forceinline__ void f_load(
    int k0, const float* __restrict__ H, const float* __restrict__ W,
    int m0, int n0, int arow, int acol, int brow, int bcol,
    float4& ra0, float4& ra1, float4& rb0, float4& rb1)
{
    const float4 z4 = make_float4(0.f, 0.f, 0.f, 0.f);
    int gm0 = m0 + arow;
    int gm1 = m0 + 64 + arow;
    ra0 = (gm0 < NN) ? *(const float4*)(H + (size_t)gm0 * LD + k0 + acol) : z4;
    ra1 = (gm1 < NN) ? *(const float4*)(H + (size_t)gm1 * LD + k0 + acol) : z4;
    int gn = n0 + bcol;
    bool nok = gn < VOC;
    int gk0 = k0 + brow;
    int gk1 = k0 + 8 + brow;
    rb0 = (gk0 < HID && nok) ? *(const float4*)(W + (size_t)gk0 * VOC + gn) : z4;
    rb1 = (gk1 < HID && nok) ? *(const float4*)(W + (size_t)gk1 * VOC + gn) : z4;
}

__device__ __forceinline__ void f_store(
    uint32_t (*As)[20], uint32_t (*Bs)[136],
    int arow, int acol, int brow, int bcol,
    const float4& ra0, const float4& ra1, const float4& rb0, const float4& rb1)
{
    uint32_t* r0 = &As[arow][acol];
    r0[0] = f2tf(ra0.x); r0[1] = f2tf(ra0.y); r0[2] = f2tf(ra0.z); r0[3] = f2tf(ra0.w);
    uint32_t* r1 = &As[64 + arow][acol];
    r1[0] = f2tf(ra1.x); r1[1] = f2tf(ra1.y); r1[2] = f2tf(ra1.z); r1[3] = f2tf(ra1.w);
    uint32_t* b0 = &Bs[brow][bcol];
    b0[0] = f2tf(rb0.x); b0[1] = f2tf(rb0.y); b0[2] = f2tf(rb0.z); b0[3] = f2tf(rb0.w);
    uint32_t* b1 = &Bs[8 + brow][bcol];
    b1[0] = f2tf(rb1.x); b1[1] = f2tf(rb1.y); b1[2] = f2tf(rb1.z); b1[3] = f2tf(rb1.w);
}

__device__ __forceinline__ void f_compute(
    const uint32_t (*As)[20], const uint32_t (*Bs)[136],
    float (&acc)[4][4][4], int wm, int wn, int lane)
{
#pragma unroll
    for (int k8 = 0; k8 < 2; k8++) {
        uint32_t a[4][4], b[4][2];
#pragma unroll
        for (int mt = 0; mt < 4; mt++) {
            int r = wm * 64 + mt * 16 + (lane >> 2);
            int c = k8 * 8 + (lane & 3);
            a[mt][0] = As[r][c];
            a[mt][1] = As[r + 8][c];
            a[mt][2] = As[r][c + 4];
            a[mt][3] = As[r + 8][c + 4];
        }
#pragma unroll
        for (int nt = 0; nt < 4; nt++) {
            int cc = wn * 32 + nt * 8 + (lane >> 2);
            int rr = k8 * 8 + (lane & 3);
            b[nt][0] = Bs[rr][cc];
            b[nt][1] = Bs[rr + 4][cc];
        }
#pragma unroll
        for (int mt = 0; mt < 4; mt++)
#pragma unroll
            for (int nt = 0; nt < 4; nt++)
                mma8(acc[mt][nt], a[mt], b[nt]);
    }
}

__global__ void __launch_bounds__(256) k_final(
    const float* __restrict__ H, const float* __restrict__ W,
    const float* __restrict__ bias, float* __restrict__ O)
{
    __shared__ uint32_t As[2][128][20];
    __shared__ uint32_t Bs[2][16][136];
    const int tid = threadIdx.x, lane = tid & 31, warp = tid >> 5;
    const int wm = warp >> 2, wn = warp & 3;
    const int m0 = blockIdx.y * 128, n0 = blockIdx.x * 128;

    float acc[4][4][4];
#pragma unroll
    for (int mt = 0; mt < 4; mt++)
#pragma unroll
        for (int nt = 0; nt < 4; nt++)
#pragma unroll
            for (int q = 0; q < 4; q++) acc[mt][nt][q] = 0.f;

    const int arow = tid >> 2;          // 0..63
    const int acol = (tid & 3) * 4;     // 0,4,8,12
    const int brow = tid >> 5;          // 0..7
    const int bcol = (tid & 31) * 4;    // 0..124

    float4 ra0, ra1, rb0, rb1;

    f_load(0, H, W, m0, n0, arow, acol, brow, bcol, ra0, ra1, rb0, rb1);
    f_store(As[0], Bs[0], arow, acol, brow, bcol, ra0, ra1, rb0, rb1);
    __syncthreads();
    for (int t = 0; t < 20; t++) {
        int cur = t & 1;
        if (t < 19)
            f_load((t + 1) * 16, H, W, m0, n0, arow, acol, brow, bcol, ra0, ra1, rb0, rb1);
        f_compute(As[cur], Bs[cur], acc, wm, wn, lane);
        if (t < 19) {
            f_store(As[cur ^ 1], Bs[cur ^ 1], arow, acol, brow, bcol, ra0, ra1, rb0, rb1);
            __syncthreads();
        }
    }

#pragma unroll
    for (int mt = 0; mt < 4; mt++) {
        int r0 = m0 + wm * 64 + mt * 16 + (lane >> 2);
#pragma unroll
        for (int nt = 0; nt < 4; nt++) {
            int c = n0 + wn * 32 + nt * 8 + (lane & 3) * 2;
            if (c >= VOC) continue;
            float bv0 = bias[c], bv1 = bias[c + 1];
            if (r0 < NN) {
                float2 v = make_float2(acc[mt][nt][0] + bv0, acc[mt][nt][1] + bv1);
                *(float2*)(O + (size_t)r0 * VOC + c) = v;
            }
            if (r0 + 8 < NN) {
                float2 v = make_float2(acc[mt][nt][2] + bv0, acc[mt][nt][3] + bv1);
                *(float2*)(O + (size_t)(r0 + 8) * VOC + c) = v;
            }
        }
    }
}

// ---------------- launcher ----------------
extern "C" void kernel_launch(void* const* d_in, const int* in_sizes, int n_in,
                              void* d_out, int out_size)
{
    (void)in_sizes; (void)n_in; (void)out_size;
    const int*   x     = (const int*)d_in[0];
    const int*   ei    = (const int*)d_in[1];
    const float* emb   = (const float*)d_in[2];
    const float* Wl    = (const float*)d_in[3];
    const float* bl    = (const float*)d_in[4];
    const float* Wr    = (const float*)d_in[5];
    const float* Wlast = (const float*)d_in[6];
    const float* blast = (const float*)d_in[7];
    float* out = (float*)d_out;

    float *h0, *h1, *agg;
    cudaGetSymbolAddress((void**)&h0, g_h0);
    cudaGetSymbolAddress((void**)&h1, g_h1);
    cudaGetSymbolAddress((void**)&agg, g_agg);

    k_zero<<<(NN + 255) / 256, 256>>>();
    k_hist<<<(NE + 255) / 256, 256>>>(ei);
    k_scan<<<1, 1024>>>();
    k_fill<<<(NE + 255) / 256, 256>>>(ei);
    k_embed<<<(NN * 32 + 127) / 128, 128>>>(x, emb);

    float* cur = h0;
    float* nxt = h1;
    for (int l = 0; l < 3; l++) {
        k_agg<<<(NN * 32 + 127) / 128, 128>>>(cur);
        k_layer<<<dim3((NN + 127) / 128, LD / 64), 256>>>(
            agg, cur, Wl + (size_t)l * HID * HID, Wr + (size_t)l * HID * HID,
            bl + (size_t)l * HID, nxt);
        float* t = cur; cur = nxt; nxt = t;
    }
    k_final<<<dim3((VOC + 127) / 128, (NN + 127) / 128), 256>>>(cur, Wlast, blast, out);
}

// round 7
// speedup vs baseline: 2.2606x; 1.0830x over previous
#include <cuda_runtime.h>
#include <cstdint>

#define NN  30000
#define NE  960000
#define HID 300
#define LD  320      // padded row stride for internal [N,H] buffers (tail zeroed)
#define VOC 10000

// ---------------- scratch (device globals: no allocs allowed) ----------------
__device__ float g_h0[NN * LD];
__device__ float g_h1[NN * LD];
__device__ float g_agg[NN * LD];
__device__ int   g_deg[NN];
__device__ float g_inv[NN];
__device__ int   g_row[NN + 1];
__device__ int   g_nxt[NN];
__device__ int   g_col[NE];
// tf32-rounded weight copies (+pad so edge-tile 16B reads stay in bounds)
__device__ float g_wl[3 * HID * HID + 16];
__device__ float g_wr[3 * HID * HID + 16];
__device__ float g_wlast[HID * VOC + 16];

// ---------------- tf32 helpers ----------------
__device__ __forceinline__ uint32_t f2tf(float f) {
    uint32_t r;
    asm("cvt.rna.tf32.f32 %0, %1;" : "=r"(r) : "f"(f));
    return r;
}
__device__ __forceinline__ float f2tff(float f) { return __uint_as_float(f2tf(f)); }

__device__ __forceinline__ void mma8(float* d, const uint32_t* a, const uint32_t* b) {
    asm volatile(
        "mma.sync.aligned.m16n8k8.row.col.f32.tf32.tf32.f32 "
        "{%0,%1,%2,%3}, {%4,%5,%6,%7}, {%8,%9}, {%0,%1,%2,%3};\n"
        : "+f"(d[0]), "+f"(d[1]), "+f"(d[2]), "+f"(d[3])
        : "r"(a[0]), "r"(a[1]), "r"(a[2]), "r"(a[3]), "r"(b[0]), "r"(b[1]));
}

__device__ __forceinline__ void cpa16(uint32_t dst, const void* src, int bytes) {
    asm volatile("cp.async.cg.shared.global [%0], [%1], 16, %2;\n"
                 :: "r"(dst), "l"(src), "r"(bytes));
}
#define CPA_COMMIT() asm volatile("cp.async.commit_group;\n" ::: "memory")

// ---------------- CSR build ----------------
__global__ void k_zero() {
    int i = blockIdx.x * blockDim.x + threadIdx.x;
    if (i < NN) g_deg[i] = 0;
}

__global__ void k_hist(const int* __restrict__ ei) {
    int e = blockIdx.x * blockDim.x + threadIdx.x;
    if (e < NE) atomicAdd(&g_deg[ei[NE + e]], 1);
}

__global__ void k_scan() {
    __shared__ int part[1024];
    int t = threadIdx.x;
    int s = t * 30;
    int e = min(s + 30, NN);
    int sum = 0;
    for (int i = s; i < e; i++) sum += g_deg[i];
    part[t] = sum;
    __syncthreads();
    for (int off = 1; off < 1024; off <<= 1) {
        int v = (t >= off) ? part[t - off] : 0;
        __syncthreads();
        part[t] += v;
        __syncthreads();
    }
    int run = (t == 0) ? 0 : part[t - 1];
    for (int i = s; i < e; i++) {
        int d = g_deg[i];
        g_row[i] = run;
        g_nxt[i] = run;
        g_inv[i] = (d > 0) ? 1.0f / (float)d : 0.0f;
        run += d;
    }
    if (t == 1023) g_row[NN] = run;
}

__global__ void k_fill(const int* __restrict__ ei) {
    int e = blockIdx.x * blockDim.x + threadIdx.x;
    if (e < NE) {
        int src = ei[e];
        int dst = ei[NE + e];
        int p = atomicAdd(&g_nxt[dst], 1);
        g_col[p] = src;
    }
}

// ---------------- one-shot weight tf32 rounding ----------------
__global__ void k_cvtw(const float* __restrict__ Wl, const float* __restrict__ Wr,
                       const float* __restrict__ Wlast) {
    int i = blockIdx.x * blockDim.x + threadIdx.x;
    const int nl = 3 * HID * HID;
    if (i < nl) {
        g_wl[i] = f2tff(Wl[i]);
        g_wr[i] = f2tff(Wr[i]);
    }
    if (i < HID * VOC) g_wlast[i] = f2tff(Wlast[i]);
}

// ---------------- embedding gather (warp per node, tf32-rounded store) -------
__global__ void k_embed(const int* __restrict__ x, const float* __restrict__ emb) {
    int node = (blockIdx.x * blockDim.x + threadIdx.x) >> 5;
    int lane = threadIdx.x & 31;
    if (node >= NN) return;
    const float4* src = (const float4*)(emb + (size_t)x[node] * HID);
    float4* dst = (float4*)(g_h0 + (size_t)node * LD);
    for (int i = lane; i < LD / 4; i += 32) {     // 80 float4 per row
        float4 v = make_float4(0.f, 0.f, 0.f, 0.f);
        if (i < HID / 4) {
            float4 s = src[i];
            v = make_float4(f2tff(s.x), f2tff(s.y), f2tff(s.z), f2tff(s.w));
        }
        dst[i] = v;
    }
}

// ---------------- scatter-mean aggregation (warp per node, CSR, float4) ------
__device__ __forceinline__ float4 round4(float4 v, float w) {
    return make_float4(f2tff(v.x * w), f2tff(v.y * w), f2tff(v.z * w), f2tff(v.w * w));
}

__global__ void k_agg(const float* __restrict__ hin) {
    int node = (blockIdx.x * blockDim.x + threadIdx.x) >> 5;
    int lane = threadIdx.x & 31;
    if (node >= NN) return;
    float4 a0 = make_float4(0.f, 0.f, 0.f, 0.f);
    float4 a1 = a0, a2 = a0;
    int s = g_row[node], e = g_row[node + 1];
    for (int j = s; j < e; j++) {
        const float4* r = (const float4*)(hin + (size_t)g_col[j] * LD);
        float4 v0 = r[lane];
        float4 v1 = r[lane + 32];
        a0.x += v0.x; a0.y += v0.y; a0.z += v0.z; a0.w += v0.w;
        a1.x += v1.x; a1.y += v1.y; a1.z += v1.z; a1.w += v1.w;
        if (lane < 16) {
            float4 v2 = r[lane + 64];
            a2.x += v2.x; a2.y += v2.y; a2.z += v2.z; a2.w += v2.w;
        }
    }
    float w = g_inv[node];
    float4* out = (float4*)(g_agg + (size_t)node * LD);
    out[lane] = round4(a0, w);
    out[lane + 32] = round4(a1, w);
    if (lane < 16) out[lane + 64] = round4(a2, w);   // pad chunks stay zero
}

// ================= layer GEMM (cp.async, 3-stage, 1 sync/iter) ==============
// BM=128, BN=64, BK=16; 256 threads, 8 warps (4x2); warp tile 32x32.
// Static smem: 3*(128*20 + 16*72)*4 = 44544 B  (< 48 KB)
#define LAW (128 * 20)
#define LBW (16 * 72)

__device__ __forceinline__ void l_issue(
    int t, uint32_t aBase, uint32_t bBase,
    const float* __restrict__ A0, const float* __restrict__ A1,
    const float* __restrict__ B0, const float* __restrict__ B1,
    int m0, int n0, int arow, int acol, int brow, int bcol)
{
    int s = (t >= 20) ? 1 : 0;
    int k0 = (t - s * 20) * 16;
    const float* A = s ? A1 : A0;
    const float* B = s ? B1 : B0;
    int gm0 = m0 + arow, gm1 = m0 + 64 + arow;
    const float* pa0 = A + (size_t)gm0 * LD + k0 + acol;
    const float* pa1 = A + (size_t)gm1 * LD + k0 + acol;
    cpa16(aBase + (uint32_t)(arow * 20 + acol) * 4, gm0 < NN ? pa0 : A, gm0 < NN ? 16 : 0);
    cpa16(aBase + (uint32_t)((arow + 64) * 20 + acol) * 4, gm1 < NN ? pa1 : A, gm1 < NN ? 16 : 0);
    int gk = k0 + brow;
    const float* pb = B + (size_t)gk * HID + n0 + bcol;
    cpa16(bBase + (uint32_t)(brow * 72 + bcol) * 4, gk < HID ? pb : B, gk < HID ? 16 : 0);
    CPA_COMMIT();
}

__device__ __forceinline__ void l_compute(
    const uint32_t (*As)[20], const uint32_t (*Bs)[72],
    float (&acc)[2][4][4], int wm, int wn, int lane)
{
#pragma unroll
    for (int k8 = 0; k8 < 2; k8++) {
        uint32_t a[2][4], b[4][2];
#pragma unroll
        for (int mt = 0; mt < 2; mt++) {
            int r = wm * 32 + mt * 16 + (lane >> 2);
            int c = k8 * 8 + (lane & 3);
            a[mt][0] = As[r][c];
            a[mt][1] = As[r + 8][c];
            a[mt][2] = As[r][c + 4];
            a[mt][3] = As[r + 8][c + 4];
        }
#pragma unroll
        for (int nt = 0; nt < 4; nt++) {
            int cc = wn * 32 + nt * 8 + (lane >> 2);
            int rr = k8 * 8 + (lane & 3);
            b[nt][0] = Bs[rr][cc];
            b[nt][1] = Bs[rr + 4][cc];
        }
#pragma unroll
        for (int mt = 0; mt < 2; mt++)
#pragma unroll
            for (int nt = 0; nt < 4; nt++)
                mma8(acc[mt][nt], a[mt], b[nt]);
    }
}

__global__ void __launch_bounds__(256) k_layer(
    const float* __restrict__ A0, const float* __restrict__ A1,
    const float* __restrict__ B0, const float* __restrict__ B1,
    const float* __restrict__ bias, float* __restrict__ C)
{
    __shared__ uint32_t As[3][128][20];
    __shared__ uint32_t Bs[3][16][72];
    const int tid = threadIdx.x, lane = tid & 31, warp = tid >> 5;
    const int wm = warp >> 1, wn = warp & 1;
    const int m0 = blockIdx.x * 128, n0 = blockIdx.y * 64;

    float acc[2][4][4];
#pragma unroll
    for (int mt = 0; mt < 2; mt++)
#pragma unroll
        for (int nt = 0; nt < 4; nt++)
#pragma unroll
            for (int q = 0; q < 4; q++) acc[mt][nt][q] = 0.f;

    const int arow = tid >> 2;          // 0..63
    const int acol = (tid & 3) * 4;     // 0,4,8,12
    const int brow = tid >> 4;          // 0..15
    const int bcol = (tid & 15) * 4;    // 0..60

    uint32_t sA = (uint32_t)__cvta_generic_to_shared(&As[0][0][0]);
    uint32_t sB = (uint32_t)__cvta_generic_to_shared(&Bs[0][0][0]);

    l_issue(0, sA, sB, A0, A1, B0, B1, m0, n0, arow, acol, brow, bcol);
    l_issue(1, sA + LAW * 4, sB + LBW * 4, A0, A1, B0, B1, m0, n0, arow, acol, brow, bcol);

    for (int t = 0; t < 40; t++) {
        if (t < 39) asm volatile("cp.async.wait_group 1;\n" ::: "memory");
        else        asm volatile("cp.async.wait_group 0;\n" ::: "memory");
        __syncthreads();
        if (t + 2 < 40) {
            int nb = (t + 2) % 3;
            l_issue(t + 2, sA + (uint32_t)nb * LAW * 4, sB + (uint32_t)nb * LBW * 4,
                    A0, A1, B0, B1, m0, n0, arow, acol, brow, bcol);
        }
        l_compute(As[t % 3], Bs[t % 3], acc, wm, wn, lane);
    }

#pragma unroll
    for (int mt = 0; mt < 2; mt++) {
        int r0 = m0 + wm * 32 + mt * 16 + (lane >> 2);
#pragma unroll
        for (int nt = 0; nt < 4; nt++) {
            int c = n0 + wn * 32 + nt * 8 + (lane & 3) * 2;   // even, < 320
            float v0 = 0.f, v1 = 0.f, v2 = 0.f, v3 = 0.f;
            if (c < HID) {   // c even, HID even -> c+1 also < HID
                float bv0 = bias[c], bv1 = bias[c + 1];
                v0 = f2tff(fmaxf(acc[mt][nt][0] + bv0, 0.f));
                v1 = f2tff(fmaxf(acc[mt][nt][1] + bv1, 0.f));
                v2 = f2tff(fmaxf(acc[mt][nt][2] + bv0, 0.f));
                v3 = f2tff(fmaxf(acc[mt][nt][3] + bv1, 0.f));
            }
            if (r0 < NN)
                *(float2*)(C + (size_t)r0 * LD + c) = make_float2(v0, v1);
            if (r0 + 8 < NN)
                *(float2*)(C + (size_t)(r0 + 8) * LD + c) = make_float2(v2, v3);
        }
    }
}

// ================= final GEMM (cp.async, 2-stage) ===========================
// BM=128, BN=128, BK=16; 256 threads, 8 warps (2x4); warp tile 64x32.
// Static smem: 2*(128*20 + 16*136)*4 = 37888 B  (< 48 KB)
#define FAW (128 * 20)
#define FBW (16 * 136)

__device__ __forceinline__ void f_issue(
    int k0, uint32_t aBase, uint32_t bBase,
    const float* __restrict__ H, const float* __restrict__ W,
    int m0, int n0, int arow, int acol, int brow, int bcol)
{
    int gm0 = m0 + arow, gm1 = m0 + 64 + arow;
    const float* pa0 = H + (size_t)gm0 * LD + k0 + acol;
    const float* pa1 = H + (size_t)gm1 * LD + k0 + acol;
    cpa16(aBase + (uint32_t)(arow * 20 + acol) * 4, gm0 < NN ? pa0 : H, gm0 < NN ? 16 : 0);
    cpa16(aBase + (uint32_t)((arow + 64) * 20 + acol) * 4, gm1 < NN ? pa1 : H, gm1 < NN ? 16 : 0);
    int gn = n0 + bcol;
    bool nok = gn < VOC;
    int gk0 = k0 + brow, gk1 = k0 + 8 + brow;
    bool ok0 = (gk0 < HID) && nok;
    bool ok1 = (gk1 < HID) && nok;
    const float* pb0 = W + (size_t)gk0 * VOC + gn;
    const float* pb1 = W + (size_t)gk1 * VOC + gn;
    cpa16(bBase + (uint32_t)(brow * 136 + bcol) * 4, ok0 ? pb0 : W, ok0 ? 16 : 0);
    cpa16(bBase + (uint32_t)((8 + brow) * 136 + bcol) * 4, ok1 ? pb1 : W, ok1 ? 16 : 0);
    CPA_COMMIT();
}

__device__ __forceinline__ void f_compute(
    const uint32_t (*As)[20], const uint32_t (*Bs)[136],
    float (&acc)[4][4][4], int wm, int wn, int lane)
{
#pragma unroll
    for (int k8 = 0; k8 < 2; k8++) {
        uint32_t a[4][4], b[4][2];
#pragma unroll
        for (int mt = 0; mt < 4; mt++) {
            int r = wm * 64 + mt * 16 + (lane >> 2);
            int c = k8 * 8 + (lane & 3);
            a[mt][0] = As[r][c];
            a[mt][1] = As[r + 8][c];
            a[mt][2] = As[r][c + 4];
            a[mt][3] = As[r + 8][c + 4];
        }
#pragma unroll
        for (int nt = 0; nt < 4; nt++) {
            int cc = wn * 32 + nt * 8 + (lane >> 2);
            int rr = k8 * 8 + (lane & 3);
            b[nt][0] = Bs[rr][cc];
            b[nt][1] = Bs[rr + 4][cc];
        }
#pragma unroll
        for (int mt = 0; mt < 4; mt++)
#pragma unroll
            for (int nt = 0; nt < 4; nt++)
                mma8(acc[mt][nt], a[mt], b[nt]);
    }
}

__global__ void __launch_bounds__(256) k_final(
    const float* __restrict__ H, const float* __restrict__ W,
    const float* __restrict__ bias, float* __restrict__ O)
{
    __shared__ uint32_t As[2][128][20];
    __shared__ uint32_t Bs[2][16][136];
    const int tid = threadIdx.x, lane = tid & 31, warp = tid >> 5;
    const int wm = warp >> 2, wn = warp & 3;
    const int m0 = blockIdx.y * 128, n0 = blockIdx.x * 128;

    float acc[4][4][4];
#pragma unroll
    for (int mt = 0; mt < 4; mt++)
#pragma unroll
        for (int nt = 0; nt < 4; nt++)
#pragma unroll
            for (int q = 0; q < 4; q++) acc[mt][nt][q] = 0.f;

    const int arow = tid >> 2;          // 0..63
    const int acol = (tid & 3) * 4;     // 0,4,8,12
    const int brow = tid >> 5;          // 0..7
    const int bcol = (tid & 31) * 4;    // 0..124

    uint32_t sA = (uint32_t)__cvta_generic_to_shared(&As[0][0][0]);
    uint32_t sB = (uint32_t)__cvta_generic_to_shared(&Bs[0][0][0]);

    f_issue(0, sA, sB, H, W, m0, n0, arow, acol, brow, bcol);
    f_issue(16, sA + FAW * 4, sB + FBW * 4, H, W, m0, n0, arow, acol, brow, bcol);

    for (int t = 0; t < 20; t++) {
        if (t < 19) asm volatile("cp.async.wait_group 1;\n" ::: "memory");
        else        asm volatile("cp.async.wait_group 0;\n" ::: "memory");
        __syncthreads();
        f_compute(As[t & 1], Bs[t & 1], acc, wm, wn, lane);
        __syncthreads();
        if (t + 2 < 20) {
            int nb = t & 1;   // buffer just consumed
            f_issue((t + 2) * 16, sA + (uint32_t)nb * FAW * 4, sB + (uint32_t)nb * FBW * 4,
                    H, W, m0, n0, arow, acol, brow, bcol);
        }
    }

#pragma unroll
    for (int mt = 0; mt < 4; mt++) {
        int r0 = m0 + wm * 64 + mt * 16 + (lane >> 2);
#pragma unroll
        for (int nt = 0; nt < 4; nt++) {
            int c = n0 + wn * 32 + nt * 8 + (lane & 3) * 2;
            if (c >= VOC) continue;
            float bv0 = bias[c], bv1 = bias[c + 1];
            if (r0 < NN) {
                float2 v = make_float2(acc[mt][nt][0] + bv0, acc[mt][nt][1] + bv1);
                *(float2*)(O + (size_t)r0 * VOC + c) = v;
            }
            if (r0 + 8 < NN) {
                float2 v = make_float2(acc[mt][nt][2] + bv0, acc[mt][nt][3] + bv1);
                *(float2*)(O + (size_t)(r0 + 8) * VOC + c) = v;
            }
        }
    }
}

// ---------------- launcher ----------------
extern "C" void kernel_launch(void* const* d_in, const int* in_sizes, int n_in,
                              void* d_out, int out_size)
{
    (void)in_sizes; (void)n_in; (void)out_size;
    const int*   x     = (const int*)d_in[0];
    const int*   ei    = (const int*)d_in[1];
    const float* emb   = (const float*)d_in[2];
    const float* Wl    = (const float*)d_in[3];
    const float* bl    = (const float*)d_in[4];
    const float* Wr    = (const float*)d_in[5];
    const float* Wlast = (const float*)d_in[6];
    const float* blast = (const float*)d_in[7];
    float* out = (float*)d_out;

    float *h0, *h1, *agg, *wl, *wr, *wlast;
    cudaGetSymbolAddress((void**)&h0, g_h0);
    cudaGetSymbolAddress((void**)&h1, g_h1);
    cudaGetSymbolAddress((void**)&agg, g_agg);
    cudaGetSymbolAddress((void**)&wl, g_wl);
    cudaGetSymbolAddress((void**)&wr, g_wr);
    cudaGetSymbolAddress((void**)&wlast, g_wlast);

    k_zero<<<(NN + 255) / 256, 256>>>();
    k_hist<<<(NE + 255) / 256, 256>>>(ei);
    k_scan<<<1, 1024>>>();
    k_fill<<<(NE + 255) / 256, 256>>>(ei);
    k_cvtw<<<(HID * VOC + 255) / 256, 256>>>(Wl, Wr, Wlast);
    k_embed<<<(NN * 32 + 127) / 128, 128>>>(x, emb);

    float* cur = h0;
    float* nxt = h1;
    for (int l = 0; l < 3; l++) {
        k_agg<<<(NN * 32 + 127) / 128, 128>>>(cur);
        k_layer<<<dim3((NN + 127) / 128, LD / 64), 256>>>(
            agg, cur, wl + (size_t)l * HID * HID, wr + (size_t)l * HID * HID,
            bl + (size_t)l * HID, nxt);
        float* t = cur; cur = nxt; nxt = t;
    }
    k_final<<<dim3((VOC + 127) / 128, (NN + 127) / 128), 256>>>(cur, wlast, blast, out);
}

// round 16
// speedup vs baseline: 3.6907x; 1.6326x over previous
#include <cuda_runtime.h>
#include <cuda_fp16.h>
#include <cstdint>

#define NN  30000
#define NE  960000
#define HID 300
#define LD  320      // padded row stride (halves) for internal [N,H] buffers
#define VOC 10000
#define HP  320      // padded weight dim

// ---------------- scratch (device globals: no allocs allowed) ----------------
__device__ __half g_h0[NN * LD];
__device__ __half g_h1[NN * LD];
__device__ __half g_agg[NN * LD];
__device__ int    g_deg[NN];
__device__ float  g_inv[NN];
__device__ int    g_row[NN + 1];
__device__ int    g_nxt[NN];
__device__ int    g_col[NE];
__device__ __half g_wlh[3 * HP * HP];   // [l][n][k] transposed, zero-padded
__device__ __half g_wrh[3 * HP * HP];
__device__ __half g_wlth[VOC * LD];     // Wlast transposed [n][k], zero-padded k

// ---------------- helpers ----------------
__device__ __forceinline__ void mma16(float* d, const uint32_t* a, const uint32_t* b) {
    asm volatile(
        "mma.sync.aligned.m16n8k16.row.col.f32.f16.f16.f32 "
        "{%0,%1,%2,%3}, {%4,%5,%6,%7}, {%8,%9}, {%0,%1,%2,%3};\n"
        : "+f"(d[0]), "+f"(d[1]), "+f"(d[2]), "+f"(d[3])
        : "r"(a[0]), "r"(a[1]), "r"(a[2]), "r"(a[3]), "r"(b[0]), "r"(b[1]));
}

__device__ __forceinline__ void cpa16(uint32_t dst, const void* src, int bytes) {
    asm volatile("cp.async.cg.shared.global [%0], [%1], 16, %2;\n"
                 :: "r"(dst), "l"(src), "r"(bytes));
}
#define CPA_COMMIT() asm volatile("cp.async.commit_group;\n" ::: "memory")

// ---------------- CSR build ----------------
__global__ void k_zero() {
    int i = blockIdx.x * blockDim.x + threadIdx.x;
    if (i < NN) g_deg[i] = 0;
}

__global__ void k_hist(const int* __restrict__ ei) {
    int e = blockIdx.x * blockDim.x + threadIdx.x;
    if (e < NE) atomicAdd(&g_deg[ei[NE + e]], 1);
}

__global__ void k_scan() {
    __shared__ int part[1024];
    int t = threadIdx.x;
    int s = t * 30;
    int e = min(s + 30, NN);
    int sum = 0;
    for (int i = s; i < e; i++) sum += g_deg[i];
    part[t] = sum;
    __syncthreads();
    for (int off = 1; off < 1024; off <<= 1) {
        int v = (t >= off) ? part[t - off] : 0;
        __syncthreads();
        part[t] += v;
        __syncthreads();
    }
    int run = (t == 0) ? 0 : part[t - 1];
    for (int i = s; i < e; i++) {
        int d = g_deg[i];
        g_row[i] = run;
        g_nxt[i] = run;
        g_inv[i] = (d > 0) ? 1.0f / (float)d : 0.0f;
        run += d;
    }
    if (t == 1023) g_row[NN] = run;
}

__global__ void k_fill(const int* __restrict__ ei) {
    int e = blockIdx.x * blockDim.x + threadIdx.x;
    if (e < NE) {
        int src = ei[e];
        int dst = ei[NE + e];
        int p = atomicAdd(&g_nxt[dst], 1);
        g_col[p] = src;
    }
}

// ---------------- weight prep: transpose + half convert ----------------
// Wl/Wr [l][K=HID][N=HID] float -> g_w*h [l][n][k] half, padded to 320x320
__global__ void k_cvtw2(const float* __restrict__ Wl, const float* __restrict__ Wr) {
    __shared__ float t1[32][33];
    __shared__ float t2[32][33];
    int n0 = blockIdx.x * 32, k0 = blockIdx.y * 32, l = blockIdx.z;
    int tx = threadIdx.x, ty = threadIdx.y;
    for (int r = ty; r < 32; r += 8) {
        int k = k0 + r, n = n0 + tx;
        bool ok = (k < HID && n < HID);
        t1[r][tx] = ok ? Wl[(size_t)l * HID * HID + (size_t)k * HID + n] : 0.f;
        t2[r][tx] = ok ? Wr[(size_t)l * HID * HID + (size_t)k * HID + n] : 0.f;
    }
    __syncthreads();
    for (int r = ty; r < 32; r += 8) {
        int n = n0 + r, k = k0 + tx;
        size_t o = (size_t)l * HP * HP + (size_t)n * HP + k;
        g_wlh[o] = __float2half_rn(t1[tx][r]);
        g_wrh[o] = __float2half_rn(t2[tx][r]);
    }
}

// Wlast [K=HID][N=VOC] float -> g_wlth [n][k] half, k padded to 320
__global__ void k_cvtwTh(const float* __restrict__ W) {
    __shared__ float tile[32][33];
    int n0 = blockIdx.x * 32, k0 = blockIdx.y * 32;
    int tx = threadIdx.x, ty = threadIdx.y;
    for (int r = ty; r < 32; r += 8) {
        int k = k0 + r, n = n0 + tx;
        tile[r][tx] = (k < HID && n < VOC) ? W[(size_t)k * VOC + n] : 0.f;
    }
    __syncthreads();
    for (int r = ty; r < 32; r += 8) {
        int n = n0 + r, k = k0 + tx;
        if (n < VOC) g_wlth[(size_t)n * LD + k] = __float2half_rn(tile[tx][r]);
    }
}

// ---------------- embedding gather (warp per node, half store) ---------------
__global__ void k_embed(const int* __restrict__ x, const float* __restrict__ emb) {
    int node = (blockIdx.x * blockDim.x + threadIdx.x) >> 5;
    int lane = threadIdx.x & 31;
    if (node >= NN) return;
    const float* src = emb + (size_t)x[node] * HID;
    uint32_t* dst = (uint32_t*)(g_h0 + (size_t)node * LD);
    for (int j = lane; j < LD / 2; j += 32) {   // 160 half2 words
        float2 v = make_float2(0.f, 0.f);
        if (2 * j + 1 < HID) v = *(const float2*)(src + 2 * j);
        __half2 h = __floats2half2_rn(v.x, v.y);
        dst[j] = *(uint32_t*)&h;
    }
}

// ---------------- scatter-mean aggregation (warp per node, half) -------------
__global__ void k_agg(const __half* __restrict__ hin) {
    int node = (blockIdx.x * blockDim.x + threadIdx.x) >> 5;
    int lane = threadIdx.x & 31;
    if (node >= NN) return;
    float2 acc[5];
#pragma unroll
    for (int q = 0; q < 5; q++) acc[q] = make_float2(0.f, 0.f);
    int s = g_row[node], e = g_row[node + 1];
    for (int j = s; j < e; j++) {
        const uint32_t* r = (const uint32_t*)(hin + (size_t)g_col[j] * LD);
#pragma unroll
        for (int q = 0; q < 5; q++) {
            uint32_t w = r[lane + 32 * q];
            float2 f = __half22float2(*(__half2*)&w);
            acc[q].x += f.x;
            acc[q].y += f.y;
        }
    }
    float wgt = g_inv[node];
    uint32_t* out = (uint32_t*)(g_agg + (size_t)node * LD);
#pragma unroll
    for (int q = 0; q < 5; q++) {
        __half2 h = __floats2half2_rn(acc[q].x * wgt, acc[q].y * wgt);
        out[lane + 32 * q] = *(uint32_t*)&h;
    }
}

// ================= layer GEMM (fp16, cp.async, 3-stage, 1 sync/iter) ========
// BM=128, BN=64, BK=32; 256 threads, 8 warps (4x2); warp tile 32x32.
// Static smem: 3*(128*20 + 64*20)*4 = 46080 B (< 48 KB)
#define LAW (128 * 20)
#define LBW (64 * 20)

__device__ __forceinline__ void l_issue(
    int t, uint32_t aBase, uint32_t bBase,
    const __half* __restrict__ A0, const __half* __restrict__ A1,
    const __half* __restrict__ B0, const __half* __restrict__ B1,
    int m0, int n0, int tid)
{
    int s = (t >= 10) ? 1 : 0;
    int k0 = (t - s * 10) * 32;          // halves
    const __half* A = s ? A1 : A0;
    const __half* B = s ? B1 : B0;
#pragma unroll
    for (int p = 0; p < 2; p++) {        // A: 128 rows x 4 chunks = 512
        int id = tid + p * 256;
        int row = id >> 2, c = id & 3;
        int gm = m0 + row;
        const __half* src = A + (size_t)gm * LD + k0 + c * 8;
        cpa16(aBase + (uint32_t)(row * 20 + c * 4) * 4,
              gm < NN ? (const void*)src : (const void*)A, gm < NN ? 16 : 0);
    }
    {                                    // B: 64 rows x 4 chunks = 256 (padded, no guard)
        int row = tid >> 2, c = tid & 3;
        const __half* src = B + (size_t)(n0 + row) * HP + k0 + c * 8;
        cpa16(bBase + (uint32_t)(row * 20 + c * 4) * 4, src, 16);
    }
    CPA_COMMIT();
}

__device__ __forceinline__ void l_compute(
    const uint32_t (*As)[20], const uint32_t (*Bs)[20],
    float (&acc)[2][4][4], int wm, int wn, int lane)
{
#pragma unroll
    for (int k16 = 0; k16 < 2; k16++) {
        uint32_t a[2][4], b[4][2];
#pragma unroll
        for (int mt = 0; mt < 2; mt++) {
            int r = wm * 32 + mt * 16 + (lane >> 2);
            int w = k16 * 8 + (lane & 3);
            a[mt][0] = As[r][w];
            a[mt][1] = As[r + 8][w];
            a[mt][2] = As[r][w + 4];
            a[mt][3] = As[r + 8][w + 4];
        }
#pragma unroll
        for (int nt = 0; nt < 4; nt++) {
            int n = wn * 32 + nt * 8 + (lane >> 2);
            int w = k16 * 8 + (lane & 3);
            b[nt][0] = Bs[n][w];
            b[nt][1] = Bs[n][w + 4];
        }
#pragma unroll
        for (int mt = 0; mt < 2; mt++)
#pragma unroll
            for (int nt = 0; nt < 4; nt++)
                mma16(acc[mt][nt], a[mt], b[nt]);
    }
}

__global__ void __launch_bounds__(256) k_layer(
    const __half* __restrict__ A0, const __half* __restrict__ A1,
    const __half* __restrict__ B0, const __half* __restrict__ B1,
    const float* __restrict__ bias, __half* __restrict__ C)
{
    __shared__ uint32_t As[3][128][20];
    __shared__ uint32_t Bs[3][64][20];
    const int tid = threadIdx.x, lane = tid & 31, warp = tid >> 5;
    const int wm = warp >> 1, wn = warp & 1;
    const int m0 = blockIdx.x * 128, n0 = blockIdx.y * 64;

    float acc[2][4][4];
#pragma unroll
    for (int mt = 0; mt < 2; mt++)
#pragma unroll
        for (int nt = 0; nt < 4; nt++)
#pragma unroll
            for (int q = 0; q < 4; q++) acc[mt][nt][q] = 0.f;

    uint32_t sA = (uint32_t)__cvta_generic_to_shared(&As[0][0][0]);
    uint32_t sB = (uint32_t)__cvta_generic_to_shared(&Bs[0][0][0]);

    l_issue(0, sA, sB, A0, A1, B0, B1, m0, n0, tid);
    l_issue(1, sA + LAW * 4, sB + LBW * 4, A0, A1, B0, B1, m0, n0, tid);

    for (int t = 0; t < 20; t++) {
        if (t < 19) asm volatile("cp.async.wait_group 1;\n" ::: "memory");
        else        asm volatile("cp.async.wait_group 0;\n" ::: "memory");
        __syncthreads();
        if (t + 2 < 20) {
            int nb = (t + 2) % 3;
            l_issue(t + 2, sA + (uint32_t)nb * LAW * 4, sB + (uint32_t)nb * LBW * 4,
                    A0, A1, B0, B1, m0, n0, tid);
        }
        l_compute(As[t % 3], Bs[t % 3], acc, wm, wn, lane);
    }

#pragma unroll
    for (int mt = 0; mt < 2; mt++) {
        int r0 = m0 + wm * 32 + mt * 16 + (lane >> 2);
#pragma unroll
        for (int nt = 0; nt < 4; nt++) {
            int c = n0 + wn * 32 + nt * 8 + (lane & 3) * 2;   // even, < 320
            float v0 = 0.f, v1 = 0.f, v2 = 0.f, v3 = 0.f;
            if (c < HID) {
                float bv0 = bias[c], bv1 = bias[c + 1];
                v0 = fmaxf(acc[mt][nt][0] + bv0, 0.f);
                v1 = fmaxf(acc[mt][nt][1] + bv1, 0.f);
                v2 = fmaxf(acc[mt][nt][2] + bv0, 0.f);
                v3 = fmaxf(acc[mt][nt][3] + bv1, 0.f);
            }
            if (r0 < NN) {
                __half2 h = __floats2half2_rn(v0, v1);
                *(uint32_t*)(C + (size_t)r0 * LD + c) = *(uint32_t*)&h;
            }
            if (r0 + 8 < NN) {
                __half2 h = __floats2half2_rn(v2, v3);
                *(uint32_t*)(C + (size_t)(r0 + 8) * LD + c) = *(uint32_t*)&h;
            }
        }
    }
}

// ================= final GEMM (fp16, cp.async, 2-stage) =====================
// BM=128, BN=128, BK=32; 256 threads, 8 warps (2x4); warp tile 64x32.
// Static smem: 2*(128*20 + 128*20)*4 = 40960 B (< 48 KB)
#define FAW (128 * 20)
#define FBW (128 * 20)

__device__ __forceinline__ void f_issue(
    int k0, uint32_t aBase, uint32_t bBase,
    const __half* __restrict__ H, const __half* __restrict__ Wt,
    int m0, int n0, int tid)
{
#pragma unroll
    for (int p = 0; p < 2; p++) {        // A: 128 rows x 4 chunks
        int id = tid + p * 256;
        int row = id >> 2, c = id & 3;
        int gm = m0 + row;
        const __half* src = H + (size_t)gm * LD + k0 + c * 8;
        cpa16(aBase + (uint32_t)(row * 20 + c * 4) * 4,
              gm < NN ? (const void*)src : (const void*)H, gm < NN ? 16 : 0);
    }
#pragma unroll
    for (int p = 0; p < 2; p++) {        // B: 128 rows x 4 chunks
        int id = tid + p * 256;
        int row = id >> 2, c = id & 3;
        int n = n0 + row;
        const __half* src = Wt + (size_t)n * LD + k0 + c * 8;
        cpa16(bBase + (uint32_t)(row * 20 + c * 4) * 4,
              n < VOC ? (const void*)src : (const void*)Wt, n < VOC ? 16 : 0);
    }
    CPA_COMMIT();
}

__device__ __forceinline__ void f_compute(
    const uint32_t (*As)[20], const uint32_t (*Bs)[20],
    float (&acc)[4][4][4], int wm, int wn, int lane)
{
#pragma unroll
    for (int k16 = 0; k16 < 2; k16++) {
        uint32_t a[4][4], b[4][2];
#pragma unroll
        for (int mt = 0; mt < 4; mt++) {
            int r = wm * 64 + mt * 16 + (lane >> 2);
            int w = k16 * 8 + (lane & 3);
            a[mt][0] = As[r][w];
            a[mt][1] = As[r + 8][w];
            a[mt][2] = As[r][w + 4];
            a[mt][3] = As[r + 8][w + 4];
        }
#pragma unroll
        for (int nt = 0; nt < 4; nt++) {
            int n = wn * 32 + nt * 8 + (lane >> 2);
            int w = k16 * 8 + (lane & 3);
            b[nt][0] = Bs[n][w];
            b[nt][1] = Bs[n][w + 4];
        }
#pragma unroll
        for (int mt = 0; mt < 4; mt++)
#pragma unroll
            for (int nt = 0; nt < 4; nt++)
                mma16(acc[mt][nt], a[mt], b[nt]);
    }
}

__global__ void __launch_bounds__(256) k_final(
    const __half* __restrict__ H, const __half* __restrict__ Wt,
    const float* __restrict__ bias, float* __restrict__ O)
{
    __shared__ uint32_t As[2][128][20];
    __shared__ uint32_t Bs[2][128][20];
    const int tid = threadIdx.x, lane = tid & 31, warp = tid >> 5;
    const int wm = warp >> 2, wn = warp & 3;
    const int m0 = blockIdx.y * 128, n0 = blockIdx.x * 128;

    float acc[4][4][4];
#pragma unroll
    for (int mt = 0; mt < 4; mt++)
#pragma unroll
        for (int nt = 0; nt < 4; nt++)
#pragma unroll
            for (int q = 0; q < 4; q++) acc[mt][nt][q] = 0.f;

    uint32_t sA = (uint32_t)__cvta_generic_to_shared(&As[0][0][0]);
    uint32_t sB = (uint32_t)__cvta_generic_to_shared(&Bs[0][0][0]);

    f_issue(0, sA, sB, H, Wt, m0, n0, tid);
    f_issue(32, sA + FAW * 4, sB + FBW * 4, H, Wt, m0, n0, tid);

    for (int t = 0; t < 10; t++) {
        if (t < 9) asm volatile("cp.async.wait_group 1;\n" ::: "memory");
        else       asm volatile("cp.async.wait_group 0;\n" ::: "memory");
        __syncthreads();
        f_compute(As[t & 1], Bs[t & 1], acc, wm, wn, lane);
        __syncthreads();
        if (t + 2 < 10) {
            int nb = t & 1;   // buffer just consumed
            f_issue((t + 2) * 32, sA + (uint32_t)nb * FAW * 4,
                    sB + (uint32_t)nb * FBW * 4, H, Wt, m0, n0, tid);
        }
    }

#pragma unroll
    for (int mt = 0; mt < 4; mt++) {
        int r0 = m0 + wm * 64 + mt * 16 + (lane >> 2);
#pragma unroll
        for (int nt = 0; nt < 4; nt++) {
            int c = n0 + wn * 32 + nt * 8 + (lane & 3) * 2;
            if (c >= VOC) continue;
            float bv0 = bias[c], bv1 = bias[c + 1];
            if (r0 < NN) {
                float2 v = make_float2(acc[mt][nt][0] + bv0, acc[mt][nt][1] + bv1);
                *(float2*)(O + (size_t)r0 * VOC + c) = v;
            }
            if (r0 + 8 < NN) {
                float2 v = make_float2(acc[mt][nt][2] + bv0, acc[mt][nt][3] + bv1);
                *(float2*)(O + (size_t)(r0 + 8) * VOC + c) = v;
            }
        }
    }
}

// ---------------- launcher ----------------
extern "C" void kernel_launch(void* const* d_in, const int* in_sizes, int n_in,
                              void* d_out, int out_size)
{
    (void)in_sizes; (void)n_in; (void)out_size;
    const int*   x     = (const int*)d_in[0];
    const int*   ei    = (const int*)d_in[1];
    const float* emb   = (const float*)d_in[2];
    const float* Wl    = (const float*)d_in[3];
    const float* bl    = (const float*)d_in[4];
    const float* Wr    = (const float*)d_in[5];
    const float* Wlast = (const float*)d_in[6];
    const float* blast = (const float*)d_in[7];
    float* out = (float*)d_out;

    __half *h0, *h1, *agg, *wlh, *wrh, *wlth;
    cudaGetSymbolAddress((void**)&h0, g_h0);
    cudaGetSymbolAddress((void**)&h1, g_h1);
    cudaGetSymbolAddress((void**)&agg, g_agg);
    cudaGetSymbolAddress((void**)&wlh, g_wlh);
    cudaGetSymbolAddress((void**)&wrh, g_wrh);
    cudaGetSymbolAddress((void**)&wlth, g_wlth);

    k_zero<<<(NN + 255) / 256, 256>>>();
    k_hist<<<(NE + 255) / 256, 256>>>(ei);
    k_scan<<<1, 1024>>>();
    k_fill<<<(NE + 255) / 256, 256>>>(ei);
    k_cvtw2<<<dim3(10, 10, 3), dim3(32, 8)>>>(Wl, Wr);
    k_cvtwTh<<<dim3((VOC + 31) / 32, 10), dim3(32, 8)>>>(Wlast);
    k_embed<<<(NN * 32 + 127) / 128, 128>>>(x, emb);

    __half* cur = h0;
    __half* nxt = h1;
    for (int l = 0; l < 3; l++) {
        k_agg<<<(NN * 32 + 127) / 128, 128>>>(cur);
        k_layer<<<dim3((NN + 127) / 128, LD / 64), 256>>>(
            agg, cur, wlh + (size_t)l * HP * HP, wrh + (size_t)l * HP * HP,
            bl + (size_t)l * HID, nxt);
        __half* t = cur; cur = nxt; nxt = t;
    }
    k_final<<<dim3((VOC + 127) / 128, (NN + 127) / 128), 256>>>(cur, wlth, blast, out);
}